// round 2
// baseline (speedup 1.0000x reference)
#include <cuda_runtime.h>

typedef unsigned long long ull;

#define Bsz  8192
#define Tlen 1024
#define NOUT 1019
#define UPAD 16

// Transposed u channel: uT[t*Bsz + b]. Static device scratch (no allocs allowed).
__device__ float g_uT[(Tlen + UPAD) * Bsz];

// ---------------- f32x2 / MUFU helpers ----------------
__device__ __forceinline__ ull f2fma(ull a, ull b, ull c) {
    ull d; asm("fma.rn.f32x2 %0, %1, %2, %3;" : "=l"(d) : "l"(a), "l"(b), "l"(c)); return d;
}
__device__ __forceinline__ ull f2add(ull a, ull b) {
    ull d; asm("add.rn.f32x2 %0, %1, %2;" : "=l"(d) : "l"(a), "l"(b)); return d;
}
__device__ __forceinline__ ull fpack(float lo, float hi) {
    ull r; asm("mov.b64 %0, {%1, %2};" : "=l"(r) : "f"(lo), "f"(hi)); return r;
}
__device__ __forceinline__ void funpack(ull v, float& lo, float& hi) {
    asm("mov.b64 {%0, %1}, %2;" : "=f"(lo), "=f"(hi) : "l"(v));
}
__device__ __forceinline__ float fex2(float x) {
    float r; asm("ex2.approx.f32 %0, %1;" : "=f"(r) : "f"(x)); return r;
}
__device__ __forceinline__ float frcp(float x) {
    float r; asm("rcp.approx.f32 %0, %1;" : "=f"(r) : "f"(x)); return r;
}

// Transformed weights:
//   w1p[p][i] = ( W1[2p][i]*S , W1[2p+1][i]*S ),  S = 2*log2(e)  (EX2 argument scale)
//   b1p likewise.
//   tanh(z) = 1 - 2*rcp(exp2(S*z) + 1); the affine (1 - 2r) is folded into layer 2:
//   w2p[j] = ( -2*W2[0][j], -2*W2[1][j] ),  b2p = ( b2[0]+sum_j W2[0][j], b2[1]+sum_j W2[1][j] )
struct Wt {
    ull w1p[3][15];
    ull b1p[3];
    ull w2p[6];
    ull b2p;
};

// x[15]: packed (v,v) pairs, layout [u0..u4 | c1_0..c1_4 | c2_0..c2_4]
// returns packed (pred_ch0, pred_ch1)
__device__ __forceinline__ ull mlp_eval(const ull* x, const Wt& w) {
    float r[6];
#pragma unroll
    for (int p = 0; p < 3; ++p) {
        ull a0 = w.b1p[p];
        ull a1 = fpack(0.f, 0.f);
#pragma unroll
        for (int i = 0; i < 7; ++i)  a0 = f2fma(w.w1p[p][i], x[i], a0);
#pragma unroll
        for (int i = 7; i < 15; ++i) a1 = f2fma(w.w1p[p][i], x[i], a1);
        ull a = f2add(a0, a1);
        float z0, z1; funpack(a, z0, z1);
        r[2 * p]     = frcp(fex2(z0) + 1.0f);
        r[2 * p + 1] = frcp(fex2(z1) + 1.0f);
    }
    ull o = w.b2p;
#pragma unroll
    for (int j = 0; j < 6; ++j) o = f2fma(w.w2p[j], fpack(r[j], r[j]), o);
    return o;
}

// ---------------- kernel 1: transpose u channel (B,T,3) -> uT (T,B) ----------------
__global__ void transpose_u(const float* __restrict__ traj) {
    __shared__ float tile[32][33];
    int tx = threadIdx.x, ty = threadIdx.y;
    int t0 = blockIdx.x * 32, b0 = blockIdx.y * 32;
    tile[ty][tx] = traj[((size_t)(b0 + ty) * Tlen + (t0 + tx)) * 3];
    __syncthreads();
    g_uT[(size_t)(t0 + ty) * Bsz + (b0 + tx)] = tile[tx][ty];
}

// ---------------- kernel 2: the rollout (1 thread per batch row) ----------------
__global__ void __launch_bounds__(128, 1)
rollout(const float* __restrict__ traj,
        const float* __restrict__ W1g, const float* __restrict__ b1g,
        const float* __restrict__ W2g, const float* __restrict__ b2g,
        float* __restrict__ out) {
    const int b = blockIdx.x * blockDim.x + threadIdx.x;
    const float S = 2.88539008177792681472f;  // 2 / ln(2)

    Wt w;
#pragma unroll
    for (int p = 0; p < 3; ++p) {
#pragma unroll
        for (int i = 0; i < 15; ++i)
            w.w1p[p][i] = fpack(W1g[(2 * p) * 15 + i] * S, W1g[(2 * p + 1) * 15 + i] * S);
        w.b1p[p] = fpack(b1g[2 * p] * S, b1g[2 * p + 1] * S);
    }
    {
        float s0 = 0.f, s1 = 0.f;
#pragma unroll
        for (int j = 0; j < 6; ++j) {
            w.w2p[j] = fpack(-2.f * W2g[j], -2.f * W2g[6 + j]);
            s0 += W2g[j];
            s1 += W2g[6 + j];
        }
        w.b2p = fpack(b2g[0] + s0, b2g[1] + s1);
    }

    // ground-truth values needed by the prologue
    float u[15];
#pragma unroll
    for (int k = 0; k < 15; ++k) u[k] = g_uT[(size_t)k * Bsz + b];
    float g1[5], g2[5];
#pragma unroll
    for (int k = 0; k < 5; ++k) {
        g1[k] = traj[((size_t)b * Tlen + k) * 3 + 1];
        g2[k] = traj[((size_t)b * Tlen + k) * 3 + 2];
    }

    ull* op = reinterpret_cast<ull*>(out) + (size_t)b * NOUT;  // float2 per step

    float p0[5], p1[5];
    auto run = [&](const float uu[5], const float c1[5], const float c2[5], int idx) {
        ull x[15];
#pragma unroll
        for (int k = 0; k < 5; ++k) {
            x[k]      = fpack(uu[k], uu[k]);
            x[5 + k]  = fpack(c1[k], c1[k]);
            x[10 + k] = fpack(c2[k], c2[k]);
        }
        ull pr = mlp_eval(x, w);
        op[idx] = pr;
        funpack(pr, p0[idx], p1[idx]);
    };

    // Prologue — replicates the reference's index pattern exactly.
    { float uu[5] = {u[0], u[1], u[2], u[3], u[4]},
            c1[5] = {g1[0], g1[1], g1[2], g1[3], g1[4]},
            c2[5] = {g2[0], g2[1], g2[2], g2[3], g2[4]};          run(uu, c1, c2, 0); }
    { float uu[5] = {u[1], u[2], u[3], u[4], u[5]},
            c1[5] = {g1[1], g1[2], g1[3], g1[4], p0[0]},
            c2[5] = {g2[1], g2[2], g2[3], g2[4], p1[0]};          run(uu, c1, c2, 1); }
    { float uu[5] = {u[2], u[3], u[4], u[6], u[7]},
            c1[5] = {g1[2], g1[3], g1[4], p0[0], p0[1]},
            c2[5] = {g2[2], g2[3], g2[4], p1[0], p1[1]};          run(uu, c1, c2, 2); }
    { float uu[5] = {u[3], u[4], u[7], u[8], u[9]},
            c1[5] = {g1[3], g1[4], p0[0], p0[1], p0[2]},
            c2[5] = {g2[3], g2[4], p1[0], p1[1], p1[2]};          run(uu, c1, c2, 3); }
    { float uu[5] = {u[4], u[8], u[9], u[10], u[11]},
            c1[5] = {g1[4], p0[0], p0[1], p0[2], p0[3]},
            c2[5] = {g2[4], p1[0], p1[1], p1[2], p1[3]};          run(uu, c1, c2, 4); }

    // Main loop state: uq[k] = (u[t+k],u[t+k]) for k=0..9 (positions 5..9 are the
    // prefetch ring hiding DRAM latency); c1w/c2w = last-5 prediction windows.
    ull uq[10], c1w[5], c2w[5];
#pragma unroll
    for (int k = 0; k < 10; ++k) uq[k] = fpack(u[5 + k], u[5 + k]);
#pragma unroll
    for (int k = 0; k < 5; ++k) { c1w[k] = fpack(p0[k], p0[k]); c2w[k] = fpack(p1[k], p1[k]); }

#pragma unroll 5
    for (int t = 5; t < NOUT; ++t) {
        float un = g_uT[(size_t)(t + 10) * Bsz + b];  // prefetch u[t+10] (padded buffer)

        ull x[15];
#pragma unroll
        for (int k = 0; k < 5; ++k) { x[k] = uq[k]; x[5 + k] = c1w[k]; x[10 + k] = c2w[k]; }

        ull pr = mlp_eval(x, w);
        op[t] = pr;

        float q0, q1; funpack(pr, q0, q1);
#pragma unroll
        for (int k = 0; k < 4; ++k) { c1w[k] = c1w[k + 1]; c2w[k] = c2w[k + 1]; }
        c1w[4] = fpack(q0, q0);
        c2w[4] = fpack(q1, q1);
#pragma unroll
        for (int k = 0; k < 9; ++k) uq[k] = uq[k + 1];
        uq[9] = fpack(un, un);
    }
}

extern "C" void kernel_launch(void* const* d_in, const int* in_sizes, int n_in,
                              void* d_out, int out_size) {
    (void)in_sizes; (void)n_in; (void)out_size;
    const float* traj = (const float*)d_in[0];
    const float* W1   = (const float*)d_in[1];
    const float* b1   = (const float*)d_in[2];
    const float* W2   = (const float*)d_in[3];
    const float* b2   = (const float*)d_in[4];

    transpose_u<<<dim3(Tlen / 32, Bsz / 32), dim3(32, 32)>>>(traj);
    rollout<<<Bsz / 128, 128>>>(traj, W1, b1, W2, b2, (float*)d_out);
}

// round 3
// speedup vs baseline: 1.0861x; 1.0861x over previous
#include <cuda_runtime.h>

typedef unsigned long long ull;

#define Bsz  8192
#define Tlen 1024
#define NOUT 1019
#define UPAD 24

// Transposed u channel: uT[t*Bsz + b]. Static device scratch (no allocs allowed).
// Padding rows (t >= 1024) are never written: .bss is zero-initialized and the
// values only enter accumulators whose z(t>1018) is never consumed.
__device__ float g_uT[(Tlen + UPAD) * Bsz];

// ---------------- f32x2 / MUFU helpers ----------------
__device__ __forceinline__ ull f2fma(ull a, ull b, ull c) {
    ull d; asm("fma.rn.f32x2 %0, %1, %2, %3;" : "=l"(d) : "l"(a), "l"(b), "l"(c)); return d;
}
__device__ __forceinline__ ull fpack(float lo, float hi) {
    ull r; asm("mov.b64 %0, {%1, %2};" : "=l"(r) : "f"(lo), "f"(hi)); return r;
}
__device__ __forceinline__ void funpack(ull v, float& lo, float& hi) {
    asm("mov.b64 {%0, %1}, %2;" : "=f"(lo), "=f"(hi) : "l"(v));
}
__device__ __forceinline__ float fex2(float x) {
    float r; asm("ex2.approx.f32 %0, %1;" : "=f"(r) : "f"(x)); return r;
}
__device__ __forceinline__ float frcp(float x) {
    float r; asm("rcp.approx.f32 %0, %1;" : "=f"(r) : "f"(x)); return r;
}

// Transformed weights. Hidden units are paired (2p,2p+1) into f32x2 lanes.
//   tanh(z) = 1 - 2*rcp(exp2(S*z)+1), S = 2*log2(e); W1,b1 pre-scaled by S,
//   the affine (1-2r) folded into layer 2 (w2 -> -2*w2, b2 += sum w2).
struct Wt {
    ull wu [5][3];   // wu[i][p]: u-window position i
    ull wc1[5][3];   // pred-ch0 window position i
    ull wc2[5][3];   // pred-ch1 window position i
    ull b1p[3];
    float w20[6], w21[6];   // layer-2 rows (transformed)
    float b20, b21;
};

// acc[3] holds packed pre-activations (already include S scale and b1).
// Produces transformed-tanh outputs o0,o1 (the final predictions).
__device__ __forceinline__ void finish(const ull a0, const ull a1, const ull a2,
                                        const Wt& w, float& o0, float& o1) {
    float z[6];
    funpack(a0, z[0], z[1]);
    funpack(a1, z[2], z[3]);
    funpack(a2, z[4], z[5]);
    float r[6];
#pragma unroll
    for (int j = 0; j < 6; ++j) r[j] = frcp(fex2(z[j]) + 1.0f);
    float e0 = fmaf(w.w20[4], r[4], fmaf(w.w20[2], r[2], fmaf(w.w20[0], r[0], w.b20)));
    float f0 = fmaf(w.w20[5], r[5], fmaf(w.w20[3], r[3], w.w20[1] * r[1]));
    float e1 = fmaf(w.w21[4], r[4], fmaf(w.w21[2], r[2], fmaf(w.w21[0], r[0], w.b21)));
    float f1 = fmaf(w.w21[5], r[5], fmaf(w.w21[3], r[3], w.w21[1] * r[1]));
    o0 = e0 + f0;
    o1 = e1 + f1;
}

// Plain (non-eager) eval for the prologue.
__device__ __forceinline__ void eval(const float uu[5], const float c1[5], const float c2[5],
                                     const Wt& w, float& o0, float& o1) {
    ull a[3] = { w.b1p[0], w.b1p[1], w.b1p[2] };
#pragma unroll
    for (int i = 0; i < 5; ++i) {
        ull xu = fpack(uu[i], uu[i]), x1 = fpack(c1[i], c1[i]), x2 = fpack(c2[i], c2[i]);
#pragma unroll
        for (int p = 0; p < 3; ++p) {
            a[p] = f2fma(w.wu [i][p], xu, a[p]);
            a[p] = f2fma(w.wc1[i][p], x1, a[p]);
            a[p] = f2fma(w.wc2[i][p], x2, a[p]);
        }
    }
    finish(a[0], a[1], a[2], w, o0, o1);
}

// ---------------- kernel 1: transpose u channel (B,T,3) -> uT (T,B) ----------------
__global__ void transpose_u(const float* __restrict__ traj) {
    __shared__ float tile[32][33];
    int tx = threadIdx.x, ty = threadIdx.y;
    int t0 = blockIdx.x * 32, b0 = blockIdx.y * 32;
    tile[ty][tx] = traj[((size_t)(b0 + ty) * Tlen + (t0 + tx)) * 3];
    __syncthreads();
    g_uT[(size_t)(t0 + ty) * Bsz + (b0 + tx)] = tile[tx][ty];
}

// ---------------- kernel 2: the rollout (1 thread per batch row, 1 warp blocks) ----------------
__global__ void __launch_bounds__(32, 1)
rollout(const float* __restrict__ traj,
        const float* __restrict__ W1g, const float* __restrict__ b1g,
        const float* __restrict__ W2g, const float* __restrict__ b2g,
        float* __restrict__ out) {
    const int b = blockIdx.x * 32 + threadIdx.x;
    const float S = 2.88539008177792681472f;  // 2 * log2(e)

    Wt w;
#pragma unroll
    for (int i = 0; i < 5; ++i)
#pragma unroll
        for (int p = 0; p < 3; ++p) {
            w.wu [i][p] = fpack(W1g[(2 * p) * 15 + i     ] * S, W1g[(2 * p + 1) * 15 + i     ] * S);
            w.wc1[i][p] = fpack(W1g[(2 * p) * 15 + 5 + i ] * S, W1g[(2 * p + 1) * 15 + 5 + i ] * S);
            w.wc2[i][p] = fpack(W1g[(2 * p) * 15 + 10 + i] * S, W1g[(2 * p + 1) * 15 + 10 + i] * S);
        }
#pragma unroll
    for (int p = 0; p < 3; ++p) w.b1p[p] = fpack(b1g[2 * p] * S, b1g[2 * p + 1] * S);
    {
        float s0 = 0.f, s1 = 0.f;
#pragma unroll
        for (int j = 0; j < 6; ++j) {
            w.w20[j] = -2.f * W2g[j];
            w.w21[j] = -2.f * W2g[6 + j];
            s0 += W2g[j];
            s1 += W2g[6 + j];
        }
        w.b20 = b2g[0] + s0;
        w.b21 = b2g[1] + s1;
    }

    // ground-truth values needed by the prologue + main-loop seed
    float u[20];
#pragma unroll
    for (int k = 0; k < 20; ++k) u[k] = g_uT[(size_t)k * Bsz + b];
    float g1[5], g2[5];
#pragma unroll
    for (int k = 0; k < 5; ++k) {
        g1[k] = traj[((size_t)b * Tlen + k) * 3 + 1];
        g2[k] = traj[((size_t)b * Tlen + k) * 3 + 2];
    }

    ull* op = reinterpret_cast<ull*>(out) + (size_t)b * NOUT;  // float2 per step

    // Prologue — replicates the reference's index pattern exactly.
    float p0[5], p1[5];
    {
        float uu[5] = {u[0], u[1], u[2], u[3], u[4]},
              c1[5] = {g1[0], g1[1], g1[2], g1[3], g1[4]},
              c2[5] = {g2[0], g2[1], g2[2], g2[3], g2[4]};
        eval(uu, c1, c2, w, p0[0], p1[0]); op[0] = fpack(p0[0], p1[0]);
    }
    {
        float uu[5] = {u[1], u[2], u[3], u[4], u[5]},
              c1[5] = {g1[1], g1[2], g1[3], g1[4], p0[0]},
              c2[5] = {g2[1], g2[2], g2[3], g2[4], p1[0]};
        eval(uu, c1, c2, w, p0[1], p1[1]); op[1] = fpack(p0[1], p1[1]);
    }
    {
        float uu[5] = {u[2], u[3], u[4], u[6], u[7]},
              c1[5] = {g1[2], g1[3], g1[4], p0[0], p0[1]},
              c2[5] = {g2[2], g2[3], g2[4], p1[0], p1[1]};
        eval(uu, c1, c2, w, p0[2], p1[2]); op[2] = fpack(p0[2], p1[2]);
    }
    {
        float uu[5] = {u[3], u[4], u[7], u[8], u[9]},
              c1[5] = {g1[3], g1[4], p0[0], p0[1], p0[2]},
              c2[5] = {g2[3], g2[4], p1[0], p1[1], p1[2]};
        eval(uu, c1, c2, w, p0[3], p1[3]); op[3] = fpack(p0[3], p1[3]);
    }
    {
        float uu[5] = {u[4], u[8], u[9], u[10], u[11]},
              c1[5] = {g1[4], p0[0], p0[1], p0[2], p0[3]},
              c2[5] = {g2[4], p1[0], p1[1], p1[2], p1[3]};
        eval(uu, c1, c2, w, p0[4], p1[4]); op[4] = fpack(p0[4], p1[4]);
    }

    // ---- eager accumulators: acc[k] = partial z(5+k), k=0..4 ----
    // z(t') = b1 + sum_i wu[i]*u[t'+i] + sum_{j=t'-5..t'-1} wc*(pred_j at pos j-(t'-5))
    ull acc[5][3];
#pragma unroll
    for (int k = 0; k < 5; ++k) {
#pragma unroll
        for (int p = 0; p < 3; ++p) acc[k][p] = w.b1p[p];
#pragma unroll
        for (int i = 0; i < 5; ++i) {
            ull xu = fpack(u[5 + k + i], u[5 + k + i]);
#pragma unroll
            for (int p = 0; p < 3; ++p) acc[k][p] = f2fma(w.wu[i][p], xu, acc[k][p]);
        }
#pragma unroll
        for (int j = 0; j < 5; ++j) {
            if (j >= k) {
                int pos = j - k;
                ull x1 = fpack(p0[j], p0[j]), x2 = fpack(p1[j], p1[j]);
#pragma unroll
                for (int p = 0; p < 3; ++p) {
                    acc[k][p] = f2fma(w.wc1[pos][p], x1, acc[k][p]);
                    acc[k][p] = f2fma(w.wc2[pos][p], x2, acc[k][p]);
                }
            }
        }
    }

    // u prefetch ring: uq[k] = (u[t+5+k], u[t+5+k]) for k=0..9 (at loop top, t current)
    ull uq[10];
#pragma unroll
    for (int k = 0; k < 10; ++k) uq[k] = fpack(u[10 + k], u[10 + k]);

#pragma unroll 5
    for (int t = 5; t < NOUT; ++t) {
        float un = g_uT[(size_t)(t + 15) * Bsz + b];  // prefetch u[t+15] (10-step distance)

        // critical path: acc[0] (already complete) -> pred(t)
        float o0, o1;
        finish(acc[0][0], acc[0][1], acc[0][2], w, o0, o1);
        op[t] = fpack(o0, o1);
        ull cp1 = fpack(o0, o0), cp2 = fpack(o1, o1);

        // shift ring: acc[k] <- z(t+1+k)
#pragma unroll
        for (int k = 0; k < 4; ++k)
#pragma unroll
            for (int p = 0; p < 3; ++p) acc[k][p] = acc[k + 1][p];

        // fresh acc[4] = z(t+5): bias + all 5 u contributions (off critical path)
#pragma unroll
        for (int p = 0; p < 3; ++p) acc[4][p] = w.b1p[p];
#pragma unroll
        for (int i = 0; i < 5; ++i)
#pragma unroll
            for (int p = 0; p < 3; ++p) acc[4][p] = f2fma(w.wu[i][p], uq[i], acc[4][p]);

        // scatter pred(t) into z(t+1)..z(t+5); k=0 (next step's input) first
#pragma unroll
        for (int k = 0; k < 5; ++k) {
            int pos = 4 - k;
#pragma unroll
            for (int p = 0; p < 3; ++p) {
                acc[k][p] = f2fma(w.wc1[pos][p], cp1, acc[k][p]);
                acc[k][p] = f2fma(w.wc2[pos][p], cp2, acc[k][p]);
            }
        }

        // shift u ring
#pragma unroll
        for (int k = 0; k < 9; ++k) uq[k] = uq[k + 1];
        uq[9] = fpack(un, un);
    }
}

extern "C" void kernel_launch(void* const* d_in, const int* in_sizes, int n_in,
                              void* d_out, int out_size) {
    (void)in_sizes; (void)n_in; (void)out_size;
    const float* traj = (const float*)d_in[0];
    const float* W1   = (const float*)d_in[1];
    const float* b1   = (const float*)d_in[2];
    const float* W2   = (const float*)d_in[3];
    const float* b2   = (const float*)d_in[4];

    transpose_u<<<dim3(Tlen / 32, Bsz / 32), dim3(32, 32)>>>(traj);
    rollout<<<Bsz / 32, 32>>>(traj, W1, b1, W2, b2, (float*)d_out);
}

// round 4
// speedup vs baseline: 1.1074x; 1.0196x over previous
#include <cuda_runtime.h>

typedef unsigned long long ull;

#define Bsz  8192
#define Tlen 1024
#define NOUT 1019
#define UPAD 24

// u channel, transposed AND duplicated: g_uD[t*Bsz + b] = (u, u) as f32x2.
// Padding rows (t >= 1024) are never written; .bss is zero-initialized and the
// resulting garbage pre-activations are finite and never stored.
__device__ ull g_uD[(Tlen + UPAD) * Bsz];

// ---------------- f32x2 / MUFU helpers ----------------
__device__ __forceinline__ ull f2fma(ull a, ull b, ull c) {
    ull d; asm("fma.rn.f32x2 %0, %1, %2, %3;" : "=l"(d) : "l"(a), "l"(b), "l"(c)); return d;
}
__device__ __forceinline__ ull f2mul(ull a, ull b) {
    ull d; asm("mul.rn.f32x2 %0, %1, %2;" : "=l"(d) : "l"(a), "l"(b)); return d;
}
__device__ __forceinline__ ull f2add(ull a, ull b) {
    ull d; asm("add.rn.f32x2 %0, %1, %2;" : "=l"(d) : "l"(a), "l"(b)); return d;
}
__device__ __forceinline__ ull fpack(float lo, float hi) {
    ull r; asm("mov.b64 %0, {%1, %2};" : "=l"(r) : "f"(lo), "f"(hi)); return r;
}
__device__ __forceinline__ void funpack(ull v, float& lo, float& hi) {
    asm("mov.b64 {%0, %1}, %2;" : "=f"(lo), "=f"(hi) : "l"(v));
}
__device__ __forceinline__ float fex2(float x) {
    float r; asm("ex2.approx.f32 %0, %1;" : "=f"(r) : "f"(x)); return r;
}
__device__ __forceinline__ float frcp(float x) {
    float r; asm("rcp.approx.f32 %0, %1;" : "=f"(r) : "f"(x)); return r;
}

// Transformed weights. Hidden units paired (2p,2p+1) into f32x2 lanes.
//   tanh(z) = 1 - 2*rcp(exp2(S*z)+1), S = 2*log2(e); W1,b1 pre-scaled by S,
//   affine (1-2r) folded into layer 2. Layer 2 packed: w2p[j] = (-2*W2[0][j], -2*W2[1][j]).
struct Wt {
    ull wu [5][3];   // u-window position i, pair p
    ull wc1[5][3];   // pred-ch0 window
    ull wc2[5][3];   // pred-ch1 window
    ull b1p[3];
    ull w2p[6];
    ull b2p;
};

// Packed pre-activations -> packed prediction (pred_ch0, pred_ch1).
__device__ __forceinline__ ull finish(ull a0, ull a1, ull a2, const Wt& w) {
    float z0, z1, z2, z3, z4, z5;
    funpack(a0, z0, z1); funpack(a1, z2, z3); funpack(a2, z4, z5);
    float r0 = frcp(fex2(z0) + 1.0f);
    float r1 = frcp(fex2(z1) + 1.0f);
    float r2 = frcp(fex2(z2) + 1.0f);
    float r3 = frcp(fex2(z3) + 1.0f);
    float r4 = frcp(fex2(z4) + 1.0f);
    float r5 = frcp(fex2(z5) + 1.0f);
    ull e = f2fma(w.w2p[4], fpack(r4, r4),
            f2fma(w.w2p[2], fpack(r2, r2),
            f2fma(w.w2p[0], fpack(r0, r0), w.b2p)));
    ull f = f2fma(w.w2p[5], fpack(r5, r5),
            f2fma(w.w2p[3], fpack(r3, r3),
            f2mul(w.w2p[1], fpack(r1, r1))));
    return f2add(e, f);
}

// Plain eval for the prologue.
__device__ __forceinline__ ull eval(const float uu[5], const float c1[5], const float c2[5],
                                    const Wt& w) {
    ull a[3] = { w.b1p[0], w.b1p[1], w.b1p[2] };
#pragma unroll
    for (int i = 0; i < 5; ++i) {
        ull xu = fpack(uu[i], uu[i]), x1 = fpack(c1[i], c1[i]), x2 = fpack(c2[i], c2[i]);
#pragma unroll
        for (int p = 0; p < 3; ++p) {
            a[p] = f2fma(w.wu [i][p], xu, a[p]);
            a[p] = f2fma(w.wc1[i][p], x1, a[p]);
            a[p] = f2fma(w.wc2[i][p], x2, a[p]);
        }
    }
    return finish(a[0], a[1], a[2], w);
}

// ---------------- kernel 1: transpose + duplicate u channel ----------------
__global__ void transpose_u(const float* __restrict__ traj) {
    __shared__ float tile[32][33];
    int tx = threadIdx.x, ty = threadIdx.y;
    int t0 = blockIdx.x * 32, b0 = blockIdx.y * 32;
    tile[ty][tx] = traj[((size_t)(b0 + ty) * Tlen + (t0 + tx)) * 3];
    __syncthreads();
    float v = tile[tx][ty];
    g_uD[(size_t)(t0 + ty) * Bsz + (b0 + tx)] = fpack(v, v);
}

// ---------------- one rollout step, all ring indices compile-time ----------------
// At step t (with J = (t-5) % 10, base multiple-of-10 + 5):
//   z(t) lives in acc[J%5]; fresh z(t+5) is rebuilt into the same slot.
//   uq[(J+i)%10] holds (u(t+5+i), u(t+5+i)); prefetch u(t+15) into slot J.
template<int J>
__device__ __forceinline__ void step(ull acc[5][3], ull uq[10], const Wt& w,
                                     const ull* __restrict__ up, ull* __restrict__ opd,
                                     int base) {
    constexpr int F = J % 5;
    ull o = finish(acc[F][0], acc[F][1], acc[F][2], w);
    if (base + J < NOUT) opd[J] = o;
    float o0, o1; funpack(o, o0, o1);
    ull cp1 = fpack(o0, o0), cp2 = fpack(o1, o1);

    // scatter pred(t) into z(t+1)..z(t+4); z(t+1) first (next step's critical input)
    {
        constexpr int s = (F + 1) % 5;
#pragma unroll
        for (int p = 0; p < 3; ++p) {
            acc[s][p] = f2fma(w.wc1[4][p], cp1, acc[s][p]);
            acc[s][p] = f2fma(w.wc2[4][p], cp2, acc[s][p]);
        }
    }
    {
        constexpr int s = (F + 2) % 5;
#pragma unroll
        for (int p = 0; p < 3; ++p) {
            acc[s][p] = f2fma(w.wc1[3][p], cp1, acc[s][p]);
            acc[s][p] = f2fma(w.wc2[3][p], cp2, acc[s][p]);
        }
    }
    {
        constexpr int s = (F + 3) % 5;
#pragma unroll
        for (int p = 0; p < 3; ++p) {
            acc[s][p] = f2fma(w.wc1[2][p], cp1, acc[s][p]);
            acc[s][p] = f2fma(w.wc2[2][p], cp2, acc[s][p]);
        }
    }
    {
        constexpr int s = (F + 4) % 5;
#pragma unroll
        for (int p = 0; p < 3; ++p) {
            acc[s][p] = f2fma(w.wc1[1][p], cp1, acc[s][p]);
            acc[s][p] = f2fma(w.wc2[1][p], cp2, acc[s][p]);
        }
    }

    // fresh z(t+5) into acc[F]: bias + 5 u terms + pred(t) at window pos 0
    ull u5 = uq[J % 10];                 // old value u(t+5), read before overwrite
    uq[J % 10] = up[(size_t)J * Bsz];    // prefetch u(t+15), first consumed 6 steps later
#pragma unroll
    for (int p = 0; p < 3; ++p) {
        ull a = f2fma(w.wu[0][p], u5, w.b1p[p]);
        a = f2fma(w.wu[1][p], uq[(J + 1) % 10], a);
        a = f2fma(w.wu[2][p], uq[(J + 2) % 10], a);
        a = f2fma(w.wu[3][p], uq[(J + 3) % 10], a);
        a = f2fma(w.wu[4][p], uq[(J + 4) % 10], a);
        a = f2fma(w.wc1[0][p], cp1, a);
        a = f2fma(w.wc2[0][p], cp2, a);
        acc[F][p] = a;
    }
}

// ---------------- kernel 2: the rollout (1 thread per batch row) ----------------
__global__ void __launch_bounds__(32, 1)
rollout(const float* __restrict__ traj,
        const float* __restrict__ W1g, const float* __restrict__ b1g,
        const float* __restrict__ W2g, const float* __restrict__ b2g,
        float* __restrict__ out) {
    const int b = blockIdx.x * 32 + threadIdx.x;
    const float S = 2.88539008177792681472f;  // 2 * log2(e)

    Wt w;
#pragma unroll
    for (int i = 0; i < 5; ++i)
#pragma unroll
        for (int p = 0; p < 3; ++p) {
            w.wu [i][p] = fpack(W1g[(2 * p) * 15 + i     ] * S, W1g[(2 * p + 1) * 15 + i     ] * S);
            w.wc1[i][p] = fpack(W1g[(2 * p) * 15 + 5 + i ] * S, W1g[(2 * p + 1) * 15 + 5 + i ] * S);
            w.wc2[i][p] = fpack(W1g[(2 * p) * 15 + 10 + i] * S, W1g[(2 * p + 1) * 15 + 10 + i] * S);
        }
#pragma unroll
    for (int p = 0; p < 3; ++p) w.b1p[p] = fpack(b1g[2 * p] * S, b1g[2 * p + 1] * S);
    {
        float s0 = 0.f, s1 = 0.f;
#pragma unroll
        for (int j = 0; j < 6; ++j) {
            w.w2p[j] = fpack(-2.f * W2g[j], -2.f * W2g[6 + j]);
            s0 += W2g[j];
            s1 += W2g[6 + j];
        }
        w.b2p = fpack(b2g[0] + s0, b2g[1] + s1);
    }

    // packed u values for prologue + ring seeds
    ull pu[20];
#pragma unroll
    for (int k = 0; k < 20; ++k) pu[k] = g_uD[(size_t)k * Bsz + b];
    float u[14], dummy;
#pragma unroll
    for (int k = 0; k < 14; ++k) funpack(pu[k], u[k], dummy);

    float g1[5], g2[5];
#pragma unroll
    for (int k = 0; k < 5; ++k) {
        g1[k] = traj[((size_t)b * Tlen + k) * 3 + 1];
        g2[k] = traj[((size_t)b * Tlen + k) * 3 + 2];
    }

    ull* op = reinterpret_cast<ull*>(out) + (size_t)b * NOUT;  // float2 per step

    // Prologue — replicates the reference's index pattern exactly.
    float p0[5], p1[5];
    {
        float uu[5] = {u[0], u[1], u[2], u[3], u[4]},
              c1[5] = {g1[0], g1[1], g1[2], g1[3], g1[4]},
              c2[5] = {g2[0], g2[1], g2[2], g2[3], g2[4]};
        ull o = eval(uu, c1, c2, w); op[0] = o; funpack(o, p0[0], p1[0]);
    }
    {
        float uu[5] = {u[1], u[2], u[3], u[4], u[5]},
              c1[5] = {g1[1], g1[2], g1[3], g1[4], p0[0]},
              c2[5] = {g2[1], g2[2], g2[3], g2[4], p1[0]};
        ull o = eval(uu, c1, c2, w); op[1] = o; funpack(o, p0[1], p1[1]);
    }
    {
        float uu[5] = {u[2], u[3], u[4], u[6], u[7]},
              c1[5] = {g1[2], g1[3], g1[4], p0[0], p0[1]},
              c2[5] = {g2[2], g2[3], g2[4], p1[0], p1[1]};
        ull o = eval(uu, c1, c2, w); op[2] = o; funpack(o, p0[2], p1[2]);
    }
    {
        float uu[5] = {u[3], u[4], u[7], u[8], u[9]},
              c1[5] = {g1[3], g1[4], p0[0], p0[1], p0[2]},
              c2[5] = {g2[3], g2[4], p1[0], p1[1], p1[2]};
        ull o = eval(uu, c1, c2, w); op[3] = o; funpack(o, p0[3], p1[3]);
    }
    {
        float uu[5] = {u[4], u[8], u[9], u[10], u[11]},
              c1[5] = {g1[4], p0[0], p0[1], p0[2], p0[3]},
              c2[5] = {g2[4], p1[0], p1[1], p1[2], p1[3]};
        ull o = eval(uu, c1, c2, w); op[4] = o; funpack(o, p0[4], p1[4]);
    }

    // eager accumulators: acc[k] = partial z(5+k), k=0..4
    ull acc[5][3];
#pragma unroll
    for (int k = 0; k < 5; ++k) {
#pragma unroll
        for (int p = 0; p < 3; ++p) acc[k][p] = w.b1p[p];
#pragma unroll
        for (int i = 0; i < 5; ++i)
#pragma unroll
            for (int p = 0; p < 3; ++p) acc[k][p] = f2fma(w.wu[i][p], pu[5 + k + i], acc[k][p]);
#pragma unroll
        for (int j = 0; j < 5; ++j) {
            if (j >= k) {
                int pos = j - k;
                ull x1 = fpack(p0[j], p0[j]), x2 = fpack(p1[j], p1[j]);
#pragma unroll
                for (int p = 0; p < 3; ++p) {
                    acc[k][p] = f2fma(w.wc1[pos][p], x1, acc[k][p]);
                    acc[k][p] = f2fma(w.wc2[pos][p], x2, acc[k][p]);
                }
            }
        }
    }

    // u ring: uq[j] = (u(10+j), u(10+j))
    ull uq[10];
#pragma unroll
    for (int j = 0; j < 10; ++j) uq[j] = pu[10 + j];

    // main loop: t = base + J, covers t = 5..1024; stores predicated to t < 1019.
    const ull* up = g_uD + (size_t)20 * Bsz + b;  // up[J*Bsz] = u(base + J + 15)
    ull* opd = op + 5;
    for (int base = 5; base < 1025; base += 10) {
        step<0>(acc, uq, w, up, opd, base);
        step<1>(acc, uq, w, up, opd, base);
        step<2>(acc, uq, w, up, opd, base);
        step<3>(acc, uq, w, up, opd, base);
        step<4>(acc, uq, w, up, opd, base);
        step<5>(acc, uq, w, up, opd, base);
        step<6>(acc, uq, w, up, opd, base);
        step<7>(acc, uq, w, up, opd, base);
        step<8>(acc, uq, w, up, opd, base);
        step<9>(acc, uq, w, up, opd, base);
        up += (size_t)10 * Bsz;
        opd += 10;
    }
}

extern "C" void kernel_launch(void* const* d_in, const int* in_sizes, int n_in,
                              void* d_out, int out_size) {
    (void)in_sizes; (void)n_in; (void)out_size;
    const float* traj = (const float*)d_in[0];
    const float* W1   = (const float*)d_in[1];
    const float* b1   = (const float*)d_in[2];
    const float* W2   = (const float*)d_in[3];
    const float* b2   = (const float*)d_in[4];

    transpose_u<<<dim3(Tlen / 32, Bsz / 32), dim3(32, 32)>>>(traj);
    rollout<<<Bsz / 32, 32>>>(traj, W1, b1, W2, b2, (float*)d_out);
}

// round 5
// speedup vs baseline: 1.2956x; 1.1700x over previous
#include <cuda_runtime.h>

typedef unsigned long long ull;

#define Bsz  8192
#define Tlen 1024
#define NOUT 1019
#define UPAD 24
#define Sc   2.88539008177792681472f   // 2 * log2(e)

// u channel, transposed AND duplicated: g_uD[t*Bsz + b] = (u, u) as f32x2.
// Rows t >= 1024 are never written (.bss zero); they only feed accumulators
// whose outputs are never stored.
__device__ ull g_uD[(Tlen + UPAD) * Bsz];

// ---------------- f32x2 / MUFU helpers ----------------
__device__ __forceinline__ ull f2fma(ull a, ull b, ull c) {
    ull d; asm("fma.rn.f32x2 %0, %1, %2, %3;" : "=l"(d) : "l"(a), "l"(b), "l"(c)); return d;
}
__device__ __forceinline__ ull fpack(float lo, float hi) {
    ull r; asm("mov.b64 %0, {%1, %2};" : "=l"(r) : "f"(lo), "f"(hi)); return r;
}
__device__ __forceinline__ void funpack(ull v, float& lo, float& hi) {
    asm("mov.b64 {%0, %1}, %2;" : "=f"(lo), "=f"(hi) : "l"(v));
}
__device__ __forceinline__ float flow(ull v) {
    float lo, hi; funpack(v, lo, hi); return lo;
}
__device__ __forceinline__ float fex2(float x) {
    float r; asm("ex2.approx.f32 %0, %1;" : "=f"(r) : "f"(x)); return r;
}
__device__ __forceinline__ float frcp(float x) {
    float r; asm("rcp.approx.f32 %0, %1;" : "=f"(r) : "f"(x)); return r;
}

// ---------------- kernel 1: transpose + duplicate u channel ----------------
__global__ void transpose_u(const float* __restrict__ traj) {
    __shared__ float tile[32][33];
    int tx = threadIdx.x, ty = threadIdx.y;
    int t0 = blockIdx.x * 32, b0 = blockIdx.y * 32;
    tile[ty][tx] = traj[((size_t)(b0 + ty) * Tlen + (t0 + tx)) * 3];
    __syncthreads();
    float v = tile[tx][ty];
    g_uD[(size_t)(t0 + ty) * Bsz + (b0 + tx)] = fpack(v, v);
}

// ---------------- per-lane weights (each lane owns hidden pair + 1 scalar) ----------------
// tanh(z) = 1 - 2*rcp(exp2(Sc*z)+1); W1,b1 pre-scaled by Sc; affine folded into
// layer 2 (w2 -> -2*w2, b2 += sum w2). Layer 2 computed as scalar partials per lane.
struct Lw {
    ull   wu_p[5], wc1_p[5], wc2_p[5], b1_p;   // packed pair (2 hidden units)
    float wu_s[5], wc1_s[5], wc2_s[5], b1_s;   // scalar hidden unit
    float w20[3], w21[3];                      // layer-2 coeffs of the 3 owned units
    float b20h, b21h;                          // folded bias (only on half 0)
};

// full 6-hidden MLP for the prologue (uniform on both lanes; reads weights from global)
__device__ __forceinline__ void mlp6(const float* __restrict__ W1g, const float* __restrict__ b1g,
                                     const float* __restrict__ W2g, float b20f, float b21f,
                                     const float uu[5], const float c1[5], const float c2[5],
                                     float& o0, float& o1) {
    float r[6];
#pragma unroll
    for (int h = 0; h < 6; ++h) {
        float z = b1g[h];
#pragma unroll
        for (int i = 0; i < 5; ++i) z = fmaf(W1g[h * 15 + i],      uu[i], z);
#pragma unroll
        for (int i = 0; i < 5; ++i) z = fmaf(W1g[h * 15 + 5 + i],  c1[i], z);
#pragma unroll
        for (int i = 0; i < 5; ++i) z = fmaf(W1g[h * 15 + 10 + i], c2[i], z);
        r[h] = frcp(fex2(z * Sc) + 1.0f);
    }
    o0 = b20f; o1 = b21f;
#pragma unroll
    for (int h = 0; h < 6; ++h) {
        o0 = fmaf(-2.0f * W2g[h],     r[h], o0);
        o1 = fmaf(-2.0f * W2g[6 + h], r[h], o1);
    }
}

// ---------------- one rollout step, all ring indices compile-time ----------------
// t = base + J. z(t) lives in (acc_p,acc_s)[J%5]; fresh z(t+5) rebuilt into same slot.
// uq[(J+i)%10] holds (u(t+5+i))x2; prefetch u(t+15) into slot J%10.
template<int J>
__device__ __forceinline__ void step(ull acc_p[5], float acc_s[5], ull uq[10], const Lw& w,
                                     const ull* __restrict__ up, ull* __restrict__ opd,
                                     int base, int half) {
    constexpr int F = J % 5;

    // finish: own 3 hidden units -> scalar layer-2 partials -> butterfly
    float z0, z1; funpack(acc_p[F], z0, z1);
    float r0 = frcp(fex2(z0) + 1.0f);
    float r1 = frcp(fex2(z1) + 1.0f);
    float rs = frcp(fex2(acc_s[F]) + 1.0f);
    float part0 = fmaf(w.w20[2], rs, fmaf(w.w20[1], r1, fmaf(w.w20[0], r0, w.b20h)));
    float part1 = fmaf(w.w21[2], rs, fmaf(w.w21[1], r1, fmaf(w.w21[0], r0, w.b21h)));
    float o0 = part0 + __shfl_xor_sync(0xFFFFFFFFu, part0, 1);
    float o1 = part1 + __shfl_xor_sync(0xFFFFFFFFu, part1, 1);
    ull o = fpack(o0, o1);
    if ((half == 0) && (base + J < NOUT)) opd[J] = o;
    ull cp1 = fpack(o0, o0), cp2 = fpack(o1, o1);

    // scatter pred(t) into z(t+1)..z(t+4); z(t+1) first (next step's critical input)
#pragma unroll
    for (int d = 1; d <= 4; ++d) {
        const int s = (F + d) % 5, pos = 5 - d;
        acc_p[s] = f2fma(w.wc1_p[pos], cp1, acc_p[s]);
        acc_p[s] = f2fma(w.wc2_p[pos], cp2, acc_p[s]);
        acc_s[s] = fmaf(w.wc1_s[pos], o0, fmaf(w.wc2_s[pos], o1, acc_s[s]));
    }

    // fresh z(t+5): bias + 5 u terms + pred(t) at window pos 0
    ull u5 = uq[J % 10];                 // u(t+5), read before overwrite
    uq[J % 10] = up[(size_t)J * Bsz];    // prefetch u(t+15), first used 6 steps later
    ull ap   = f2fma(w.wu_p[0], u5, w.b1_p);
    float as = fmaf(w.wu_s[0], flow(u5), w.b1_s);
#pragma unroll
    for (int i = 1; i < 5; ++i) {
        ull uv = uq[(J + i) % 10];
        ap = f2fma(w.wu_p[i], uv, ap);
        as = fmaf(w.wu_s[i], flow(uv), as);
    }
    ap = f2fma(w.wc1_p[0], cp1, ap);
    ap = f2fma(w.wc2_p[0], cp2, ap);
    as = fmaf(w.wc1_s[0], o0, fmaf(w.wc2_s[0], o1, as));
    acc_p[F] = ap;
    acc_s[F] = as;
}

// ---------------- kernel 2: the rollout (2 lanes per batch row) ----------------
__global__ void __launch_bounds__(32, 1)
rollout(const float* __restrict__ traj,
        const float* __restrict__ W1g, const float* __restrict__ b1g,
        const float* __restrict__ W2g, const float* __restrict__ b2g,
        float* __restrict__ out) {
    const int lane = threadIdx.x;
    const int half = lane & 1;
    const int b    = blockIdx.x * 16 + (lane >> 1);

    // layer-2 bias fold (needed by both prologue and main loop)
    float s0 = 0.f, s1 = 0.f;
#pragma unroll
    for (int j = 0; j < 6; ++j) { s0 += W2g[j]; s1 += W2g[6 + j]; }
    const float b20f = b2g[0] + s0, b21f = b2g[1] + s1;

    // per-lane main-loop weights: pair rows (2*half, 2*half+1), scalar row 4+half
    const int pr0 = 2 * half, pr1 = 2 * half + 1, sc = 4 + half;
    Lw w;
#pragma unroll
    for (int i = 0; i < 5; ++i) {
        w.wu_p [i] = fpack(W1g[pr0 * 15 + i     ] * Sc, W1g[pr1 * 15 + i     ] * Sc);
        w.wc1_p[i] = fpack(W1g[pr0 * 15 + 5 + i ] * Sc, W1g[pr1 * 15 + 5 + i ] * Sc);
        w.wc2_p[i] = fpack(W1g[pr0 * 15 + 10 + i] * Sc, W1g[pr1 * 15 + 10 + i] * Sc);
        w.wu_s [i] = W1g[sc * 15 + i     ] * Sc;
        w.wc1_s[i] = W1g[sc * 15 + 5 + i ] * Sc;
        w.wc2_s[i] = W1g[sc * 15 + 10 + i] * Sc;
    }
    w.b1_p = fpack(b1g[pr0] * Sc, b1g[pr1] * Sc);
    w.b1_s = b1g[sc] * Sc;
    w.w20[0] = -2.f * W2g[pr0]; w.w20[1] = -2.f * W2g[pr1]; w.w20[2] = -2.f * W2g[sc];
    w.w21[0] = -2.f * W2g[6 + pr0]; w.w21[1] = -2.f * W2g[6 + pr1]; w.w21[2] = -2.f * W2g[6 + sc];
    w.b20h = (half == 0) ? b20f : 0.f;
    w.b21h = (half == 0) ? b21f : 0.f;

    // packed u for seeds (+ scalar views) and ground-truth c1/c2 for prologue
    ull pu[20];
#pragma unroll
    for (int k = 0; k < 20; ++k) pu[k] = g_uD[(size_t)k * Bsz + b];
    float u[12];
#pragma unroll
    for (int k = 0; k < 12; ++k) u[k] = flow(pu[k]);
    float g1[5], g2[5];
#pragma unroll
    for (int k = 0; k < 5; ++k) {
        g1[k] = traj[((size_t)b * Tlen + k) * 3 + 1];
        g2[k] = traj[((size_t)b * Tlen + k) * 3 + 2];
    }

    ull* op = reinterpret_cast<ull*>(out) + (size_t)b * NOUT;  // float2 per step

    // Prologue — replicates the reference's index pattern exactly (computed
    // identically on both lanes; lane 0 stores).
    float p0[5], p1[5];
    {
        float uu[5] = {u[0], u[1], u[2], u[3], u[4]},
              c1[5] = {g1[0], g1[1], g1[2], g1[3], g1[4]},
              c2[5] = {g2[0], g2[1], g2[2], g2[3], g2[4]};
        mlp6(W1g, b1g, W2g, b20f, b21f, uu, c1, c2, p0[0], p1[0]);
    }
    {
        float uu[5] = {u[1], u[2], u[3], u[4], u[5]},
              c1[5] = {g1[1], g1[2], g1[3], g1[4], p0[0]},
              c2[5] = {g2[1], g2[2], g2[3], g2[4], p1[0]};
        mlp6(W1g, b1g, W2g, b20f, b21f, uu, c1, c2, p0[1], p1[1]);
    }
    {
        float uu[5] = {u[2], u[3], u[4], u[6], u[7]},
              c1[5] = {g1[2], g1[3], g1[4], p0[0], p0[1]},
              c2[5] = {g2[2], g2[3], g2[4], p1[0], p1[1]};
        mlp6(W1g, b1g, W2g, b20f, b21f, uu, c1, c2, p0[2], p1[2]);
    }
    {
        float uu[5] = {u[3], u[4], u[7], u[8], u[9]},
              c1[5] = {g1[3], g1[4], p0[0], p0[1], p0[2]},
              c2[5] = {g2[3], g2[4], p1[0], p1[1], p1[2]};
        mlp6(W1g, b1g, W2g, b20f, b21f, uu, c1, c2, p0[3], p1[3]);
    }
    {
        float uu[5] = {u[4], u[8], u[9], u[10], u[11]},
              c1[5] = {g1[4], p0[0], p0[1], p0[2], p0[3]},
              c2[5] = {g2[4], p1[0], p1[1], p1[2], p1[3]};
        mlp6(W1g, b1g, W2g, b20f, b21f, uu, c1, c2, p0[4], p1[4]);
    }
    if (half == 0) {
#pragma unroll
        for (int k = 0; k < 5; ++k) op[k] = fpack(p0[k], p1[k]);
    }

    // eager accumulators for own units: (acc_p,acc_s)[k] = partial z(5+k)
    ull P0[5], P1[5];
#pragma unroll
    for (int j = 0; j < 5; ++j) { P0[j] = fpack(p0[j], p0[j]); P1[j] = fpack(p1[j], p1[j]); }
    ull acc_p[5]; float acc_s[5];
#pragma unroll
    for (int k = 0; k < 5; ++k) {
        ull ap = w.b1_p; float as = w.b1_s;
#pragma unroll
        for (int i = 0; i < 5; ++i) {
            ap = f2fma(w.wu_p[i], pu[5 + k + i], ap);
            as = fmaf(w.wu_s[i], flow(pu[5 + k + i]), as);
        }
#pragma unroll
        for (int j = 0; j < 5; ++j) {
            if (j >= k) {
                int pos = j - k;
                ap = f2fma(w.wc1_p[pos], P0[j], ap);
                ap = f2fma(w.wc2_p[pos], P1[j], ap);
                as = fmaf(w.wc1_s[pos], p0[j], fmaf(w.wc2_s[pos], p1[j], as));
            }
        }
        acc_p[k] = ap; acc_s[k] = as;
    }

    // u ring: uq[j] = (u(10+j))x2
    ull uq[10];
#pragma unroll
    for (int j = 0; j < 10; ++j) uq[j] = pu[10 + j];

    // main loop: t = base + J, covers t = 5..1024; stores predicated to t < 1019.
    const ull* up = g_uD + (size_t)20 * Bsz + b;  // up[J*Bsz] = u(base + J + 15)
    ull* opd = op + 5;
    for (int base = 5; base < 1025; base += 10) {
        step<0>(acc_p, acc_s, uq, w, up, opd, base, half);
        step<1>(acc_p, acc_s, uq, w, up, opd, base, half);
        step<2>(acc_p, acc_s, uq, w, up, opd, base, half);
        step<3>(acc_p, acc_s, uq, w, up, opd, base, half);
        step<4>(acc_p, acc_s, uq, w, up, opd, base, half);
        step<5>(acc_p, acc_s, uq, w, up, opd, base, half);
        step<6>(acc_p, acc_s, uq, w, up, opd, base, half);
        step<7>(acc_p, acc_s, uq, w, up, opd, base, half);
        step<8>(acc_p, acc_s, uq, w, up, opd, base, half);
        step<9>(acc_p, acc_s, uq, w, up, opd, base, half);
        up += (size_t)10 * Bsz;
        opd += 10;
    }
}

extern "C" void kernel_launch(void* const* d_in, const int* in_sizes, int n_in,
                              void* d_out, int out_size) {
    (void)in_sizes; (void)n_in; (void)out_size;
    const float* traj = (const float*)d_in[0];
    const float* W1   = (const float*)d_in[1];
    const float* b1   = (const float*)d_in[2];
    const float* W2   = (const float*)d_in[3];
    const float* b2   = (const float*)d_in[4];

    transpose_u<<<dim3(Tlen / 32, Bsz / 32), dim3(32, 32)>>>(traj);
    rollout<<<(2 * Bsz) / 32, 32>>>(traj, W1, b1, W2, b2, (float*)d_out);
}